// round 2
// baseline (speedup 1.0000x reference)
#include <cuda_runtime.h>

#define BATCH 64
#define CH    128
#define TLEN  10000
#define TT    128
#define PITCH 129   // CH + 1 -> conflict-free row AND column SMEM access

// Scratch (allocation-free rule: __device__ globals)
__device__ float g_m[BATCH * TLEN];      // channel-mean per (b, t)  (2.56 MB)
__device__ float g_S1[BATCH * CH];       // sum of y over time
__device__ float g_S2[BATCH * CH];       // sum of y^2 over time
__device__ float g_A[BATCH * CH];        // 1/std
__device__ float g_Bc[BATCH * CH];       // mean * (1/std)

__global__ void k0_zero() {
    int i = blockIdx.x * blockDim.x + threadIdx.x;
    if (i < BATCH * CH) { g_S1[i] = 0.f; g_S2[i] = 0.f; }
}

// One block = one (batch, 128-wide time tile). Full channel dim in SMEM.
__global__ void __launch_bounds__(256) k1_stats(const float* __restrict__ x) {
    extern __shared__ float sm[];
    float* tile  = sm;                   // CH * PITCH
    float* mrow  = tile + CH * PITCH;    // TT
    float* mpart = mrow + TT;            // TT
    float* p1    = mpart + TT;           // CH
    float* p2    = p1 + CH;              // CH

    const int b   = blockIdx.y;
    const int t0  = blockIdx.x * TT;
    const int tid = threadIdx.x;
    const int tvalid = min(TT, TLEN - t0);
    const float* xb = x + (size_t)b * CH * TLEN + t0;

    // Load tile: warp lanes span t (coalesced 128B LDG, conflict-free STS).
    #pragma unroll 8
    for (int it = 0; it < 64; ++it) {
        int i = it * 256 + tid;
        int c = i >> 7;        // fixed within a warp
        int t = i & 127;       // consecutive across lanes
        float v = (t < tvalid) ? xb[(size_t)c * TLEN + t] : 0.f;
        tile[c * PITCH + t] = v;
    }
    __syncthreads();

    // Channel mean per t: 2 thread-halves each sum 64 channels (column access,
    // conflict-free: fixed c per iteration, t consecutive across lanes).
    {
        int t    = tid & 127;
        int half = tid >> 7;
        float s = 0.f;
        int cbeg = half * 64;
        #pragma unroll 16
        for (int c = cbeg; c < cbeg + 64; ++c) s += tile[c * PITCH + t];
        if (half) mpart[t] = s;
        __syncthreads();
        if (!half) {
            float m = (s + mpart[t]) * (1.f / 128.f);
            mrow[t] = m;                                   // 0 for padded t
            if (t < tvalid) g_m[(size_t)b * TLEN + t0 + t] = m;
        }
        __syncthreads();
    }

    // Per-channel partial sums of y = x - m and y^2.
    // Warp lanes span 32 consecutive channels at the same t:
    // bank = (c*129 + t) % 32 = (c + t) % 32 -> 32 distinct banks.
    const int w = tid >> 5, l = tid & 31;
    const int c  = ((w & 3) << 5) + l;
    const int ts = (w >> 2) * 64;
    const float* row = tile + c * PITCH;
    float s1 = 0.f, s2 = 0.f;
    #pragma unroll 16
    for (int t = ts; t < ts + 64; ++t) {
        float y = row[t] - mrow[t];     // padded entries: 0 - 0 = 0
        s1 += y;
        s2 = fmaf(y, y, s2);
    }
    if (w >> 2) { p1[c] = s1; p2[c] = s2; }
    __syncthreads();
    if (!(w >> 2)) {
        atomicAdd(&g_S1[b * CH + c], s1 + p1[c]);
        atomicAdd(&g_S2[b * CH + c], s2 + p2[c]);
    }
}

__global__ void k2_finalize() {
    int i = blockIdx.x * blockDim.x + threadIdx.x;
    if (i < BATCH * CH) {
        float mean = g_S1[i] * (1.f / TLEN);
        float var  = fmaf(-mean, mean, g_S2[i] * (1.f / TLEN));
        float inv  = (var > 0.f) ? (1.f / sqrtf(var)) : 1.f;
        g_A[i]  = inv;
        g_Bc[i] = mean * inv;
    }
}

// out = (x - m - mean) * inv, float4-vectorized (10000 % 4 == 0).
__global__ void __launch_bounds__(256) k3_apply(const float* __restrict__ x,
                                                float* __restrict__ out) {
    const int row = blockIdx.y;                 // b*CH + c
    const int b   = row >> 7;
    const int j4  = blockIdx.x * blockDim.x + threadIdx.x;
    if (j4 >= TLEN / 4) return;
    const float inv  = __ldg(&g_A[row]);
    const float bias = __ldg(&g_Bc[row]);
    const size_t off  = (size_t)row * TLEN + (size_t)j4 * 4;
    const size_t moff = (size_t)b   * TLEN + (size_t)j4 * 4;
    const float4 xv = *(const float4*)(x + off);
    const float4 mv = *(const float4*)(g_m + moff);
    float4 o;
    o.x = fmaf(xv.x - mv.x, inv, -bias);
    o.y = fmaf(xv.y - mv.y, inv, -bias);
    o.z = fmaf(xv.z - mv.z, inv, -bias);
    o.w = fmaf(xv.w - mv.w, inv, -bias);
    *(float4*)(out + off) = o;
}

extern "C" void kernel_launch(void* const* d_in, const int* in_sizes, int n_in,
                              void* d_out, int out_size) {
    const float* x = (const float*)d_in[0];
    float* out = (float*)d_out;

    const int smem_bytes = (CH * PITCH + 2 * TT + 2 * CH) * (int)sizeof(float); // 68096
    cudaFuncSetAttribute(k1_stats, cudaFuncAttributeMaxDynamicSharedMemorySize,
                         smem_bytes);

    k0_zero<<<(BATCH * CH + 255) / 256, 256>>>();
    dim3 g1((TLEN + TT - 1) / TT, BATCH);         // (79, 64)
    k1_stats<<<g1, 256, smem_bytes>>>(x);
    k2_finalize<<<(BATCH * CH + 255) / 256, 256>>>();
    dim3 g3((TLEN / 4 + 255) / 256, BATCH * CH);  // (10, 8192)
    k3_apply<<<g3, 256>>>(x, out);
}